// round 17
// baseline (speedup 1.0000x reference)
#include <cuda_runtime.h>
#include <cuda_fp16.h>
#include <math.h>

#define MAXN 50000

// scratch (device globals — no allocation allowed)
__device__ float g_chis[MAXN];
__device__ float g_sigA[MAXN];
__device__ float g_epsA[MAXN];
__device__ float g_w[MAXN * 16];
__device__ float g_scal[2];   // pot, vdw

// pre-split phase3 weights: hi [0,5760), lo [5760,11520)
__device__ __half gWall[11520];
// pre-split phase1 combined W1 [k=64][h=80 pad 88] * 1/sqrt(64): hi/lo
__device__ __half gW1all[11264];

// ---- constant weights for epilogues / nodes ----
__constant__ float cWc2[16];
__constant__ float cWs2[32];
__constant__ float cWe2[32];
__constant__ float cWw1[17 * 16];

__device__ __forceinline__ float siluf(float z) {
    return __fdividef(z, 1.0f + __expf(-z));
}
__device__ __forceinline__ float sigmf(float z) {
    return __fdividef(1.0f, 1.0f + __expf(-z));
}
__device__ __forceinline__ void prefetchL2(const void* p) {
    asm volatile("prefetch.global.L2 [%0];" :: "l"(p));
}

// ---- MMA helpers ----
__device__ __forceinline__ unsigned smaddr(const void* p) {
    unsigned a;
    asm("{ .reg .u64 t; cvta.to.shared.u64 t, %1; cvt.u32.u64 %0, t; }"
        : "=r"(a) : "l"(p));
    return a;
}
__device__ __forceinline__ void ldsm_x4(unsigned& r0, unsigned& r1,
                                        unsigned& r2, unsigned& r3, unsigned addr) {
    asm volatile("ldmatrix.sync.aligned.m8n8.x4.shared.b16 {%0,%1,%2,%3}, [%4];"
                 : "=r"(r0), "=r"(r1), "=r"(r2), "=r"(r3) : "r"(addr));
}
__device__ __forceinline__ void ldsm_x2t(unsigned& r0, unsigned& r1, unsigned addr) {
    asm volatile("ldmatrix.sync.aligned.m8n8.x2.trans.shared.b16 {%0,%1}, [%2];"
                 : "=r"(r0), "=r"(r1) : "r"(addr));
}
// x4 trans: rows = lane 0..31; (r0,r1) rows 0-15, (r2,r3) rows 16-31
__device__ __forceinline__ void ldsm_x4t(unsigned& r0, unsigned& r1,
                                         unsigned& r2, unsigned& r3, unsigned addr) {
    asm volatile("ldmatrix.sync.aligned.m8n8.x4.trans.shared.b16 {%0,%1,%2,%3}, [%4];"
                 : "=r"(r0), "=r"(r1), "=r"(r2), "=r"(r3) : "r"(addr));
}
__device__ __forceinline__ void mma16816(float* c,
                                         unsigned a0, unsigned a1, unsigned a2, unsigned a3,
                                         unsigned b0, unsigned b1) {
    asm volatile(
        "mma.sync.aligned.m16n8k16.row.col.f32.f16.f16.f32 "
        "{%0,%1,%2,%3}, {%4,%5,%6,%7}, {%8,%9}, {%0,%1,%2,%3};"
        : "+f"(c[0]), "+f"(c[1]), "+f"(c[2]), "+f"(c[3])
        : "r"(a0), "r"(a1), "r"(a2), "r"(a3), "r"(b0), "r"(b1));
}
// packed split: hi = f16x2(a,b) (a low), lo = f16x2 residuals
__device__ __forceinline__ void split2(float a, float b, unsigned& hi, unsigned& lo) {
    asm("cvt.rn.f16x2.f32 %0, %1, %2;" : "=r"(hi) : "f"(b), "f"(a));
    __half2 hh = *reinterpret_cast<__half2*>(&hi);
    float2 f = __half22float2(hh);
    float ra = a - f.x, rb = b - f.y;
    asm("cvt.rn.f16x2.f32 %0, %1, %2;" : "=r"(lo) : "f"(rb), "f"(ra));
}
__device__ __forceinline__ unsigned long long pk64(unsigned lo32, unsigned hi32) {
    return ((unsigned long long)hi32 << 32) | lo32;
}

// ---------------------------------------------------------------------------
// Init: zero node accumulators + split both phase-weight banks (one launch).
// ---------------------------------------------------------------------------
__global__ void k_init(const float* __restrict__ Wx1, const float* __restrict__ Wx2,
                       const float* __restrict__ Wx3, const float* __restrict__ Wc1,
                       const float* __restrict__ Ws1, const float* __restrict__ We1,
                       int N) {
    int i = blockIdx.x * blockDim.x + threadIdx.x;
    if (i < N) { g_chis[i] = 0.f; g_sigA[i] = 0.f; g_epsA[i] = 0.f; }
    if (i < 2) g_scal[i] = 0.f;

    const float s80 = 0.11180339887498949f;
    const float s32 = 0.17677669529663689f;
    const float s64 = 0.125f;

    if (i < 5760) {
        int row = i / 40, n = i - row * 40;
        float v = 0.f;
        if (n < 32) {
            if (row < 80)       v = Wx1[row * 32 + n] * s80;
            else if (row < 112) v = Wx2[(row - 80) * 32 + n] * s32;
            else                v = Wx3[(row - 112) * 32 + n] * s32;
        }
        __half h = __float2half_rn(v);
        gWall[i] = h;
        gWall[5760 + i] = __float2half_rn(v - __half2float(h));
    }
    if (i < 5632) {
        int k = i / 88, h = i - k * 88;
        float v = 0.f;
        if (h < 16)      v = Wc1[k * 16 + h] * s64;
        else if (h < 48) v = Ws1[k * 32 + (h - 16)] * s64;
        else if (h < 80) v = We1[k * 32 + (h - 48)] * s64;
        __half hh = __float2half_rn(v);
        gW1all[i] = hh;
        gW1all[5632 + i] = __float2half_rn(v - __half2float(hh));
    }
}

// ---------------------------------------------------------------------------
// Phase 1 (tensor cores): 256 threads, 8 tiles x 128 edges per CTA, 3 CTAs/SM.
// x4t B-ldsm batching; V copy folded in.
// ---------------------------------------------------------------------------
#define LDA1 136
#define LDW1 88
#define P1_TILES 8
#define P1_SMEM (128 * LDA1 * 2 + 11264 * 2 + 320)

__global__ __launch_bounds__(256, 3) void k_phase1(
    const float* __restrict__ x, const int* __restrict__ senders,
    const float* __restrict__ V, float* __restrict__ out_V, int E)
{
    extern __shared__ __align__(16) char dyn1[];
    __half* sA = reinterpret_cast<__half*>(dyn1);
    __half* sW = sA + 128 * LDA1;
    float* sw2s = reinterpret_cast<float*>(sW + 11264);

    int tid = threadIdx.x;
    {
        const uint4* src = reinterpret_cast<const uint4*>(gW1all);
        uint4* dst = reinterpret_cast<uint4*>(sW);
        for (int i = tid; i < 11264 / 8; i += 256) dst[i] = src[i];
    }
    if (tid < 80) {
        const float s32c = 0.17677669529663689f;
        float v;
        if (tid < 16)      v = cWc2[tid] * 0.25f;
        else if (tid < 48) v = cWs2[tid - 16] * s32c;
        else               v = cWe2[tid - 48] * s32c;
        sw2s[tid] = v;
    }
    const __half* sWh = sW;
    const __half* sWl = sW + 5632;

    int lane = tid & 31;
    int wid  = tid >> 5;
    int rb   = wid * 16;
    int col  = (lane & 3) * 2;

#pragma unroll 1
    for (int t = 0; t < P1_TILES; t++) {
        int eb = (blockIdx.x * P1_TILES + t) * 128;
        if (eb >= E) break;

        // ---- stage A: x (cols 0..63 hi, 64..127 lo), ST.64 ----
        for (int i = tid; i < 128 * 16; i += 256) {
            int r = i >> 4, q = i & 15;
            int e = eb + r;
            float4 v = make_float4(0.f, 0.f, 0.f, 0.f);
            if (e < E) v = reinterpret_cast<const float4*>(x)[(size_t)e * 16 + q];
            unsigned h01, l01, h23, l23;
            split2(v.x, v.y, h01, l01);
            split2(v.z, v.w, h23, l23);
            __half* Ar = sA + r * LDA1;
            *reinterpret_cast<unsigned long long*>(Ar + q * 4)      = pk64(h01, h23);
            *reinterpret_cast<unsigned long long*>(Ar + 64 + q * 4) = pk64(l01, l23);
        }
        __syncthreads();

        // ---- prefetch next tile into L2 ----
        if (t + 1 < P1_TILES) {
            int ebn = eb + 128;
            if (ebn + (tid >> 1) < E)
                prefetchL2(x + (size_t)ebn * 64 + tid * 32);
            if (tid < 4 && ebn + tid * 32 < E)
                prefetchL2(senders + ebn + tid * 32);
        }

        // ---- A fragments: 8 k-blocks (0..3 hi, 4..7 lo) ----
        unsigned a[8][4];
        {
            const __half* ap = sA + (rb + (lane & 15)) * LDA1 + (lane >> 4) * 8;
#pragma unroll
            for (int kb = 0; kb < 8; kb++)
                ldsm_x4(a[kb][0], a[kb][1], a[kb][2], a[kb][3], smaddr(ap + kb * 16));
        }

        // ---- per-nt: MMA chain (x4t B loads) then immediate epilogue ----
        float sc0 = 0.f, sc1 = 0.f, ss0 = 0.f, ss1 = 0.f, se0 = 0.f, se1 = 0.f;
#pragma unroll
        for (int nt = 0; nt < 10; nt++) {
            float c[4] = {0.f, 0.f, 0.f, 0.f};
#pragma unroll
            for (int kb2 = 0; kb2 < 2; kb2++) {
                unsigned bh0, bh1, bh2, bh3, bl0, bl1, bl2, bl3;
                ldsm_x4t(bh0, bh1, bh2, bh3,
                         smaddr(sWh + (kb2 * 32 + lane) * LDW1 + nt * 8));
                ldsm_x4t(bl0, bl1, bl2, bl3,
                         smaddr(sWl + (kb2 * 32 + lane) * LDW1 + nt * 8));
                int kb = kb2 * 2;
                mma16816(c, a[kb][0], a[kb][1], a[kb][2], a[kb][3], bh0, bh1);
                mma16816(c, a[kb + 4][0], a[kb + 4][1], a[kb + 4][2], a[kb + 4][3], bh0, bh1);
                mma16816(c, a[kb][0], a[kb][1], a[kb][2], a[kb][3], bl0, bl1);
                mma16816(c, a[kb + 1][0], a[kb + 1][1], a[kb + 1][2], a[kb + 1][3], bh2, bh3);
                mma16816(c, a[kb + 5][0], a[kb + 5][1], a[kb + 5][2], a[kb + 5][3], bh2, bh3);
                mma16816(c, a[kb + 1][0], a[kb + 1][1], a[kb + 1][2], a[kb + 1][3], bl2, bl3);
            }
            float w0 = sw2s[nt * 8 + col];
            float w1 = sw2s[nt * 8 + col + 1];
            float v0 = siluf(c[0]) * w0 + siluf(c[1]) * w1;
            float v1 = siluf(c[2]) * w0 + siluf(c[3]) * w1;
            if (nt < 2)      { sc0 += v0; sc1 += v1; }
            else if (nt < 6) { ss0 += v0; ss1 += v1; }
            else             { se0 += v0; se1 += v1; }
        }

        // quad reduce
#pragma unroll
        for (int m = 1; m < 4; m <<= 1) {
            sc0 += __shfl_xor_sync(0xffffffffu, sc0, m);
            sc1 += __shfl_xor_sync(0xffffffffu, sc1, m);
            ss0 += __shfl_xor_sync(0xffffffffu, ss0, m);
            ss1 += __shfl_xor_sync(0xffffffffu, ss1, m);
            se0 += __shfl_xor_sync(0xffffffffu, se0, m);
            se1 += __shfl_xor_sync(0xffffffffu, se1, m);
        }
        if ((lane & 3) == 0) {
            int e0 = eb + rb + (lane >> 2);
            int e1 = e0 + 8;
            if (e0 < E) {
                int s = senders[e0];
                atomicAdd(&g_chis[s], sc0);
                atomicAdd(&g_sigA[s], ss0);
                atomicAdd(&g_epsA[s], se0);
            }
            if (e1 < E) {
                int s = senders[e1];
                atomicAdd(&g_chis[s], sc1);
                atomicAdd(&g_sigA[s], ss1);
                atomicAdd(&g_epsA[s], se1);
            }
        }

        // ---- V copy (independent; balances DRAM between phases) ----
        for (int i = tid; i < 128 * 4; i += 256) {
            int e = eb + (i >> 2);
            if (e < E) {
                reinterpret_cast<float4*>(out_V)[(size_t)e * 4 + (i & 3)] =
                    reinterpret_cast<const float4*>(V)[(size_t)e * 4 + (i & 3)];
            }
        }
        __syncthreads();
    }
}

// ---------------------------------------------------------------------------
// Phase 2 (unchanged): per-node charges / pot / vdw / w embedding.
// ---------------------------------------------------------------------------
__global__ __launch_bounds__(256) void k_nodes(
    const int* __restrict__ species, const float* __restrict__ radius,
    const float* __restrict__ hardness, const float* __restrict__ charge_embed,
    float* __restrict__ out_charges, int N)
{
    int n = blockIdx.x * 256 + threadIdx.x;
    float potc = 0.f, vdwc = 0.f;
    if (n < N) {
        int sp = species[n];
        float gamma = fmaf(4.f, radius[sp], 0.5f);
        float hv = hardness[sp];
        float hard = fmaxf(hv, 0.f) + log1pf(__expf(-fabsf(hv)));
        float chis = g_chis[n];
        float q = -chis / hard;
        potc = 0.5f * (hard + 1.f / gamma) * q * q + chis * q;
        float sgv = sigmf(g_sigA[n]) * 0.15f + 0.15f;
        float epv = sigmf(g_epsA[n]) * 1.7f + 0.3f;
        vdwc = sgv * epv;
        out_charges[n] = q;

        const float s17 = 0.24253562503633297f;
        const float* ce = charge_embed + (size_t)sp * 16;
        float wv[16];
        float qs = q * s17;
#pragma unroll
        for (int j = 0; j < 16; j++) wv[j] = qs * cWw1[j];
#pragma unroll
        for (int i = 0; i < 16; i++) {
            float c = ce[i] * s17;
#pragma unroll
            for (int j = 0; j < 16; j++)
                wv[j] = fmaf(c, cWw1[(1 + i) * 16 + j], wv[j]);
        }
        float4* wout = reinterpret_cast<float4*>(g_w) + (size_t)n * 4;
#pragma unroll
        for (int j = 0; j < 4; j++)
            wout[j] = make_float4(wv[4 * j], wv[4 * j + 1], wv[4 * j + 2], wv[4 * j + 3]);
    }
#pragma unroll
    for (int off = 16; off > 0; off >>= 1) {
        potc += __shfl_down_sync(0xffffffffu, potc, off);
        vdwc += __shfl_down_sync(0xffffffffu, vdwc, off);
    }
    if ((threadIdx.x & 31) == 0) {
        atomicAdd(&g_scal[0], potc);
        atomicAdd(&g_scal[1], vdwc);
    }
}

// ---------------------------------------------------------------------------
// Phase 3: tensor cores, 256 threads, 8 tiles x 128 edges per CTA, 3 CTAs/SM,
// x4t B-ldsm batching, prefetch pipeline, vectors staged via smem.
// ---------------------------------------------------------------------------
#define LDA 168
#define LDW 40
#define P3_TILES 8
#define P3_SMEM (128 * LDA * 2 + 11520 * 2 + 128 * 3 * 4)

__global__ __launch_bounds__(256, 3) void k_phase3(
    const float* __restrict__ x, const float* __restrict__ vectors,
    const int* __restrict__ senders,
    float* __restrict__ out_x, float* __restrict__ out_pv, int E)
{
    extern __shared__ __align__(16) char dyn3[];
    __half* sA = reinterpret_cast<__half*>(dyn3);
    __half* sW = sA + 128 * LDA;
    float* sV = reinterpret_cast<float*>(sW + 11520);

    int tid = threadIdx.x;

    if (blockIdx.x == 0 && tid == 0) {
        out_pv[0] = g_scal[0];
        out_pv[1] = g_scal[1];
    }

    {
        const uint4* src = reinterpret_cast<const uint4*>(gWall);
        uint4* dst = reinterpret_cast<uint4*>(sW);
        for (int i = tid; i < 11520 / 8; i += 256) dst[i] = src[i];
    }

    const __half* sW1h = sW;
    const __half* sW2h = sW + 80 * LDW;
    const __half* sW3h = sW + 112 * LDW;
    const __half* sW1l = sW + 5760;
    const __half* sW2l = sW + 5760 + 80 * LDW;
    const __half* sW3l = sW + 5760 + 112 * LDW;

    int lane = tid & 31;
    int wid  = tid >> 5;
    int rb   = wid * 16;
    int brow = lane & 15;

#pragma unroll 1
    for (int t = 0; t < P3_TILES; t++) {
        int eb = (blockIdx.x * P3_TILES + t) * 128;
        if (eb >= E) break;

        // ---- stage vectors (coalesced) ----
        for (int i = tid; i < 128 * 3; i += 256) {
            int e = eb + i / 3;
            sV[i] = (e < E) ? vectors[(size_t)eb * 3 + i] : 2.0f;
        }

        // ---- stage A: x + w-gather (ST.64) ----
        for (int i = tid; i < 128 * 16; i += 256) {
            int r = i >> 4, q = i & 15;
            int e = eb + r;
            float4 v = make_float4(0.f, 0.f, 0.f, 0.f);
            if (e < E) v = reinterpret_cast<const float4*>(x)[(size_t)e * 16 + q];
            unsigned h01, l01, h23, l23;
            split2(v.x, v.y, h01, l01);
            split2(v.z, v.w, h23, l23);
            __half* Ar = sA + r * LDA;
            *reinterpret_cast<unsigned long long*>(Ar + q * 4)      = pk64(h01, h23);
            *reinterpret_cast<unsigned long long*>(Ar + 80 + q * 4) = pk64(l01, l23);
        }
        for (int i = tid; i < 128 * 4; i += 256) {
            int r = i >> 2, q = i & 3;
            int e = eb + r;
            float4 v = make_float4(0.f, 0.f, 0.f, 0.f);
            if (e < E) {
                int s = senders[e];
                v = reinterpret_cast<const float4*>(g_w)[(size_t)s * 4 + q];
            }
            unsigned h01, l01, h23, l23;
            split2(v.x, v.y, h01, l01);
            split2(v.z, v.w, h23, l23);
            __half* Ar = sA + r * LDA;
            *reinterpret_cast<unsigned long long*>(Ar + 64 + q * 4)  = pk64(h01, h23);
            *reinterpret_cast<unsigned long long*>(Ar + 144 + q * 4) = pk64(l01, l23);
        }
        __syncthreads();

        // ---- prefetch next tile (x, senders, resolved g_w rows) ----
        if (t + 1 < P3_TILES) {
            int ebn = eb + 128;
            if (ebn + (tid >> 1) < E)
                prefetchL2(x + (size_t)ebn * 64 + tid * 32);
            if (tid < 4 && ebn + tid * 32 < E)
                prefetchL2(senders + ebn + tid * 32);
            if (tid < 128) {
                int e = ebn + tid;
                if (e < E) {
                    int sn = senders[e];
                    prefetchL2(g_w + (size_t)sn * 16);
                }
            }
        }

        unsigned a[10][4];
        {
            const __half* ap = sA + (rb + (lane & 15)) * LDA + (lane >> 4) * 8;
#pragma unroll
            for (int kb = 0; kb < 10; kb++)
                ldsm_x4(a[kb][0], a[kb][1], a[kb][2], a[kb][3], smaddr(ap + kb * 16));
        }

        // ---- layer 1: kb2 x4t pairs + k5=4 tail x2t ----
        float c1[4][4];
#pragma unroll
        for (int nt = 0; nt < 4; nt++)
#pragma unroll
            for (int j = 0; j < 4; j++) c1[nt][j] = 0.f;
#pragma unroll
        for (int nt = 0; nt < 4; nt++) {
#pragma unroll
            for (int kb2 = 0; kb2 < 2; kb2++) {
                unsigned bh0, bh1, bh2, bh3, bl0, bl1, bl2, bl3;
                ldsm_x4t(bh0, bh1, bh2, bh3,
                         smaddr(sW1h + (kb2 * 32 + lane) * LDW + nt * 8));
                ldsm_x4t(bl0, bl1, bl2, bl3,
                         smaddr(sW1l + (kb2 * 32 + lane) * LDW + nt * 8));
                int k5 = kb2 * 2;
                mma16816(c1[nt], a[k5][0], a[k5][1], a[k5][2], a[k5][3], bh0, bh1);
                mma16816(c1[nt], a[k5 + 5][0], a[k5 + 5][1], a[k5 + 5][2], a[k5 + 5][3], bh0, bh1);
                mma16816(c1[nt], a[k5][0], a[k5][1], a[k5][2], a[k5][3], bl0, bl1);
                mma16816(c1[nt], a[k5 + 1][0], a[k5 + 1][1], a[k5 + 1][2], a[k5 + 1][3], bh2, bh3);
                mma16816(c1[nt], a[k5 + 6][0], a[k5 + 6][1], a[k5 + 6][2], a[k5 + 6][3], bh2, bh3);
                mma16816(c1[nt], a[k5 + 1][0], a[k5 + 1][1], a[k5 + 1][2], a[k5 + 1][3], bl2, bl3);
            }
            {
                unsigned bh0, bh1, bl0, bl1;
                ldsm_x2t(bh0, bh1, smaddr(sW1h + (64 + brow) * LDW + nt * 8));
                ldsm_x2t(bl0, bl1, smaddr(sW1l + (64 + brow) * LDW + nt * 8));
                mma16816(c1[nt], a[4][0], a[4][1], a[4][2], a[4][3], bh0, bh1);
                mma16816(c1[nt], a[9][0], a[9][1], a[9][2], a[9][3], bh0, bh1);
                mma16816(c1[nt], a[4][0], a[4][1], a[4][2], a[4][3], bl0, bl1);
            }
        }

        unsigned ah[2][4], al[2][4];
#pragma unroll
        for (int p = 0; p < 2; p++) {
            split2(siluf(c1[2 * p][0]),     siluf(c1[2 * p][1]),     ah[p][0], al[p][0]);
            split2(siluf(c1[2 * p][2]),     siluf(c1[2 * p][3]),     ah[p][1], al[p][1]);
            split2(siluf(c1[2 * p + 1][0]), siluf(c1[2 * p + 1][1]), ah[p][2], al[p][2]);
            split2(siluf(c1[2 * p + 1][2]), siluf(c1[2 * p + 1][3]), ah[p][3], al[p][3]);
        }

        // ---- layer 2 (one x4t covers all 32 k-rows) ----
        float c2[4][4];
#pragma unroll
        for (int nt = 0; nt < 4; nt++)
#pragma unroll
            for (int j = 0; j < 4; j++) c2[nt][j] = 0.f;
#pragma unroll
        for (int nt = 0; nt < 4; nt++) {
            unsigned bh0, bh1, bh2, bh3, bl0, bl1, bl2, bl3;
            ldsm_x4t(bh0, bh1, bh2, bh3, smaddr(sW2h + lane * LDW + nt * 8));
            ldsm_x4t(bl0, bl1, bl2, bl3, smaddr(sW2l + lane * LDW + nt * 8));
            mma16816(c2[nt], ah[0][0], ah[0][1], ah[0][2], ah[0][3], bh0, bh1);
            mma16816(c2[nt], al[0][0], al[0][1], al[0][2], al[0][3], bh0, bh1);
            mma16816(c2[nt], ah[0][0], ah[0][1], ah[0][2], ah[0][3], bl0, bl1);
            mma16816(c2[nt], ah[1][0], ah[1][1], ah[1][2], ah[1][3], bh2, bh3);
            mma16816(c2[nt], al[1][0], al[1][1], al[1][2], al[1][3], bh2, bh3);
            mma16816(c2[nt], ah[1][0], ah[1][1], ah[1][2], ah[1][3], bl2, bl3);
        }
#pragma unroll
        for (int p = 0; p < 2; p++) {
            split2(siluf(c2[2 * p][0]),     siluf(c2[2 * p][1]),     ah[p][0], al[p][0]);
            split2(siluf(c2[2 * p][2]),     siluf(c2[2 * p][3]),     ah[p][1], al[p][1]);
            split2(siluf(c2[2 * p + 1][0]), siluf(c2[2 * p + 1][1]), ah[p][2], al[p][2]);
            split2(siluf(c2[2 * p + 1][2]), siluf(c2[2 * p + 1][3]), ah[p][3], al[p][3]);
        }

        // ---- layer 3 (no activation) ----
        float c3[4][4];
#pragma unroll
        for (int nt = 0; nt < 4; nt++)
#pragma unroll
            for (int j = 0; j < 4; j++) c3[nt][j] = 0.f;
#pragma unroll
        for (int nt = 0; nt < 4; nt++) {
            unsigned bh0, bh1, bh2, bh3, bl0, bl1, bl2, bl3;
            ldsm_x4t(bh0, bh1, bh2, bh3, smaddr(sW3h + lane * LDW + nt * 8));
            ldsm_x4t(bl0, bl1, bl2, bl3, smaddr(sW3l + lane * LDW + nt * 8));
            mma16816(c3[nt], ah[0][0], ah[0][1], ah[0][2], ah[0][3], bh0, bh1);
            mma16816(c3[nt], al[0][0], al[0][1], al[0][2], al[0][3], bh0, bh1);
            mma16816(c3[nt], ah[0][0], ah[0][1], ah[0][2], ah[0][3], bl0, bl1);
            mma16816(c3[nt], ah[1][0], ah[1][1], ah[1][2], ah[1][3], bh2, bh3);
            mma16816(c3[nt], al[1][0], al[1][1], al[1][2], al[1][3], bh2, bh3);
            mma16816(c3[nt], ah[1][0], ah[1][1], ah[1][2], ah[1][3], bl2, bl3);
        }

        // ---- envelope (vectors from smem) + store ----
        int r0 = rb + (lane >> 2);
        int e0 = eb + r0, e1 = e0 + 8;
        float env0 = 0.f, env1 = 0.f;
        {
            float vx = sV[r0 * 3], vy = sV[r0 * 3 + 1], vz = sV[r0 * 3 + 2];
            float u = sqrtf(vx * vx + vy * vy + vz * vz);
            if (u < 1.f) {
                float u2 = u * u, u6 = u2 * u2 * u2;
                env0 = 1.f + u6 * (-28.f + u * (48.f - 21.f * u));
            }
        }
        {
            int r1 = r0 + 8;
            float vx = sV[r1 * 3], vy = sV[r1 * 3 + 1], vz = sV[r1 * 3 + 2];
            float u = sqrtf(vx * vx + vy * vy + vz * vz);
            if (u < 1.f) {
                float u2 = u * u, u6 = u2 * u2 * u2;
                env1 = 1.f + u6 * (-28.f + u * (48.f - 21.f * u));
            }
        }
        int col0 = (lane & 3) * 2;
#pragma unroll
        for (int nt = 0; nt < 4; nt++) {
            int c = nt * 8 + col0;
            if (e0 < E) {
                float2 v = make_float2(env0 * c3[nt][0], env0 * c3[nt][1]);
                *reinterpret_cast<float2*>(out_x + (size_t)e0 * 32 + c) = v;
            }
            if (e1 < E) {
                float2 v = make_float2(env1 * c3[nt][2], env1 * c3[nt][3]);
                *reinterpret_cast<float2*>(out_x + (size_t)e1 * 32 + c) = v;
            }
        }
        __syncthreads();
    }
}

// ---------------------------------------------------------------------------
// Launch. Output layout: x_out[E*32] | V[E*16] | charges[N] | pot | vdw
// ---------------------------------------------------------------------------
extern "C" void kernel_launch(void* const* d_in, const int* in_sizes, int n_in,
                              void* d_out, int out_size) {
    const float* vectors = (const float*)d_in[0];
    const float* x       = (const float*)d_in[1];
    const float* V       = (const float*)d_in[2];
    const int*   senders = (const int*)d_in[3];
    const int*   species = (const int*)d_in[4];
    const float* radius  = (const float*)d_in[5];
    const float* hardness= (const float*)d_in[6];
    const float* cembed  = (const float*)d_in[7];
    const float* Wc1 = (const float*)d_in[8];
    const float* Ws1 = (const float*)d_in[10];
    const float* We1 = (const float*)d_in[12];
    const float* Ww1 = (const float*)d_in[14];
    const float* Wx1 = (const float*)d_in[15];
    const float* Wx2 = (const float*)d_in[16];
    const float* Wx3 = (const float*)d_in[17];

    const int E = in_sizes[3];
    const int N = in_sizes[4];

    cudaFuncSetAttribute(k_phase1, cudaFuncAttributeMaxDynamicSharedMemorySize, P1_SMEM);
    cudaFuncSetAttribute(k_phase3, cudaFuncAttributeMaxDynamicSharedMemorySize, P3_SMEM);

    cudaMemcpyToSymbolAsync(cWc2, d_in[9],  16 * 4, 0, cudaMemcpyDeviceToDevice, 0);
    cudaMemcpyToSymbolAsync(cWs2, d_in[11], 32 * 4, 0, cudaMemcpyDeviceToDevice, 0);
    cudaMemcpyToSymbolAsync(cWe2, d_in[13], 32 * 4, 0, cudaMemcpyDeviceToDevice, 0);
    cudaMemcpyToSymbolAsync(cWw1, Ww1, 17 * 16 * 4, 0, cudaMemcpyDeviceToDevice, 0);

    float* out = (float*)d_out;
    float* out_x       = out;
    float* out_V       = out + (size_t)E * 32;
    float* out_charges = out + (size_t)E * 48;
    float* out_pv      = out + (size_t)E * 48 + N;

    int nb_n  = (N + 255) / 256;
    int nb_e1 = (E + 128 * P1_TILES - 1) / (128 * P1_TILES);
    int nb_e3 = (E + 128 * P3_TILES - 1) / (128 * P3_TILES);

    k_init<<<nb_n, 256>>>(Wx1, Wx2, Wx3, Wc1, Ws1, We1, N);
    k_phase1<<<nb_e1, 256, P1_SMEM>>>(x, senders, V, out_V, E);
    k_nodes<<<nb_n, 256>>>(species, radius, hardness, cembed, out_charges, N);
    k_phase3<<<nb_e3, 256, P3_SMEM>>>(x, vectors, senders, out_x, out_pv, E);
}